// round 14
// baseline (speedup 1.0000x reference)
#include <cuda_runtime.h>
#include <cuda_bf16.h>
#include <mma.h>
#include <cstdint>
#include <math.h>

using namespace nvcuda;

#define EPSV 1e-4f
#define BROWS 8192
#define FDIM 512
#define PDIM 64
#define CDIM 100
#define USTRIDE 112

typedef unsigned long long ull;

__device__ float g_si[BROWS * PDIM];
__device__ float g_u2[PDIM * USTRIDE];

// ---- packed f32x2 helpers (scan) ----
__device__ __forceinline__ ull pk2(float lo, float hi) {
    ull r; asm("mov.b64 %0, {%1, %2};" : "=l"(r) : "f"(lo), "f"(hi)); return r;
}
__device__ __forceinline__ float2 upk2(ull v) {
    float2 r; asm("mov.b64 {%0, %1}, %2;" : "=f"(r.x), "=f"(r.y) : "l"(v)); return r;
}
__device__ __forceinline__ ull fma2(ull a, ull b, ull c) {
    ull d; asm("fma.rn.f32x2 %0, %1, %2, %3;" : "=l"(d) : "l"(a), "l"(b), "l"(c)); return d;
}
__device__ __forceinline__ ull mul2(ull a, ull b) {
    ull d; asm("mul.rn.f32x2 %0, %1, %2;" : "=l"(d) : "l"(a), "l"(b)); return d;
}
__device__ __forceinline__ ull add2(ull a, ull b) {
    ull d; asm("add.rn.f32x2 %0, %1, %2;" : "=l"(d) : "l"(a), "l"(b)); return d;
}
__device__ __forceinline__ float frcp(float x) {
    float r; asm("rcp.approx.f32 %0, %1;" : "=f"(r) : "f"(x)); return r;
}
__device__ __forceinline__ unsigned int s2u(const void* p) {
    return (unsigned int)__cvta_generic_to_shared(p);
}
__device__ __forceinline__ void cpa16(unsigned int dst, const void* src) {
    asm volatile("cp.async.cg.shared.global [%0], [%1], 16;" :: "r"(dst), "l"(src));
}

// truncation split: H = top-16-bit bf16 pair (PRMT), L = rn(v - hi) pair
__device__ __forceinline__ void tsplit4(float4 v, uint2& H, uint2& L) {
    unsigned u0 = __float_as_uint(v.x), u1 = __float_as_uint(v.y);
    unsigned u2 = __float_as_uint(v.z), u3 = __float_as_uint(v.w);
    H.x = __byte_perm(u0, u1, 0x7632);
    H.y = __byte_perm(u2, u3, 0x7632);
    float l0 = v.x - __uint_as_float(u0 & 0xFFFF0000u);
    float l1 = v.y - __uint_as_float(u1 & 0xFFFF0000u);
    float l2 = v.z - __uint_as_float(u2 & 0xFFFF0000u);
    float l3 = v.w - __uint_as_float(u3 & 0xFFFF0000u);
    asm("cvt.rn.bf16x2.f32 %0, %1, %2;" : "=r"(L.x) : "f"(l1), "f"(l0));
    asm("cvt.rn.bf16x2.f32 %0, %1, %2;" : "=r"(L.y) : "f"(l3), "f"(l2));
}

// ================= fused split + wmma GEMM + si : 256 threads =================
// smem layout identical to R13 (103 KB): staging fp32 2x32KB @0, bf16 tiles, consts
#define SM_XH 65536
#define SM_XL 74752
#define SM_WH 83968
#define SM_WL 93184
#define SM_CON 102400
#define MSM_BYTES 103424
#define BSTR 72

__global__ __launch_bounds__(256)
void mma_si_kernel(const float* __restrict__ x, const float* __restrict__ w,
                   const float* __restrict__ xi, const float* __restrict__ eta,
                   const float* __restrict__ beta) {
    extern __shared__ __align__(128) char smem[];
    const int tid = threadIdx.x;

    // block 128: u table
    if (blockIdx.x == 128) {
        if (tid < PDIM) {
            const float* br = beta + (size_t)tid * CDIM;
            float* ur = g_u2 + tid * USTRIDE;
            float s2 = 0.f;
            #pragma unroll 4
            for (int c = 0; c < CDIM; c++) { float v = br[c]; float bb = v * v; ur[c] = bb; s2 += bb; }
            float rs = 1.f / s2;
            #pragma unroll 4
            for (int c = 0; c < CDIM; c++) ur[c] *= rs;
            #pragma unroll
            for (int c = CDIM; c < USTRIDE; c++) ur[c] = 0.f;
        }
        return;
    }

    float* dsmf = (float*)smem;
    __nv_bfloat16* sxh = (__nv_bfloat16*)(smem + SM_XH);
    __nv_bfloat16* sxl = (__nv_bfloat16*)(smem + SM_XL);
    __nv_bfloat16* swh = (__nv_bfloat16*)(smem + SM_WH);
    __nv_bfloat16* swl = (__nv_bfloat16*)(smem + SM_WL);
    float* sGam = (float*)(smem + SM_CON);
    float* sAlp = sGam + 64;
    float* sWn  = sAlp + 64;
    float* sXn  = sWn + 64;

    const int warp = tid >> 5;          // 0..7
    const int wm = warp >> 1;           // 0..3 (16-row slice)
    const int wn = warp & 1;            // 0..1 (32-col slice)
    const int r0 = blockIdx.x * 64;
    const unsigned FULL = 0xffffffffu;

    if (tid < PDIM) {
        float e = eta[tid];
        sGam[tid] = e * e;
        sAlp[tid] = 1.f / (1.f + __expf(-xi[tid]));
    }

    // stage chunk 0 (fp32 x + w)
    #pragma unroll
    for (int it = 0; it < 4; it++) {
        int f = tid + it * 256;
        int row = f >> 4, c4 = (f & 15) << 2;
        cpa16(s2u(smem + f * 16), x + (size_t)(r0 + row) * FDIM + c4);
        cpa16(s2u(smem + 16384 + f * 16), w + (size_t)row * FDIM + c4);
    }
    asm volatile("cp.async.commit_group;" ::: "memory");

    wmma::fragment<wmma::accumulator, 16, 16, 16, float> acc[2];
    #pragma unroll
    for (int nt = 0; nt < 2; nt++) wmma::fill_fragment(acc[nt], 0.f);

    float xnp[4] = {0.f, 0.f, 0.f, 0.f};
    float wnp[4] = {0.f, 0.f, 0.f, 0.f};

    #pragma unroll 1
    for (int ch = 0; ch < FDIM / 64; ch++) {
        const int buf = ch & 1;
        asm volatile("cp.async.wait_group 0;" ::: "memory");
        __syncthreads();   // staging[buf] ready AND tiles free

        if (ch < FDIM / 64 - 1) {
            const int nb = buf ^ 1;
            #pragma unroll
            for (int it = 0; it < 4; it++) {
                int f = tid + it * 256;
                int row = f >> 4, c4 = (f & 15) << 2;
                int kc = (ch + 1) * 64;
                cpa16(s2u(smem + nb * 32768 + f * 16),
                      x + (size_t)(r0 + row) * FDIM + kc + c4);
                cpa16(s2u(smem + nb * 32768 + 16384 + f * 16),
                      w + (size_t)row * FDIM + kc + c4);
            }
            asm volatile("cp.async.commit_group;" ::: "memory");
        }

        // convert fp32 staging -> bf16 h/l tiles (truncation split); norm partials
        const float* sxf = dsmf + buf * 8192;
        const float* swf = sxf + 4096;
        #pragma unroll
        for (int it = 0; it < 4; it++) {
            int f = tid + it * 256;
            int row = f >> 4, c = (f & 15) << 2;
            float4 v = *(const float4*)(sxf + f * 4);
            uint2 H, L;
            tsplit4(v, H, L);
            *(uint2*)(sxh + row * BSTR + c) = H;
            *(uint2*)(sxl + row * BSTR + c) = L;
            xnp[it] += v.x * v.x + v.y * v.y + v.z * v.z + v.w * v.w;

            float4 u = *(const float4*)(swf + f * 4);
            tsplit4(u, H, L);
            *(uint2*)(swh + row * BSTR + c) = H;
            *(uint2*)(swl + row * BSTR + c) = L;
            wnp[it] += u.x * u.x + u.y * u.y + u.z * u.z + u.w * u.w;
        }
        __syncthreads();   // tiles ready

        #pragma unroll
        for (int kk = 0; kk < 4; kk++) {
            wmma::fragment<wmma::matrix_a, 16, 16, 16, __nv_bfloat16, wmma::row_major> ah, al;
            wmma::load_matrix_sync(ah, sxh + wm * 16 * BSTR + kk * 16, BSTR);
            wmma::load_matrix_sync(al, sxl + wm * 16 * BSTR + kk * 16, BSTR);
            #pragma unroll
            for (int nt = 0; nt < 2; nt++) {
                int ncol = wn * 32 + nt * 16;
                wmma::fragment<wmma::matrix_b, 16, 16, 16, __nv_bfloat16, wmma::col_major> bh, bl;
                wmma::load_matrix_sync(bh, swh + ncol * BSTR + kk * 16, BSTR);
                wmma::load_matrix_sync(bl, swl + ncol * BSTR + kk * 16, BSTR);
                wmma::mma_sync(acc[nt], ah, bh, acc[nt]);
                wmma::mma_sync(acc[nt], ah, bl, acc[nt]);
                wmma::mma_sync(acc[nt], al, bh, acc[nt]);
            }
        }
    }

    // reduce norm partials: row (tid>>4) + 16*it, owned by 16 consecutive tids
    #pragma unroll
    for (int it = 0; it < 4; it++) {
        float vx = xnp[it], vw = wnp[it];
        vx += __shfl_xor_sync(FULL, vx, 1); vw += __shfl_xor_sync(FULL, vw, 1);
        vx += __shfl_xor_sync(FULL, vx, 2); vw += __shfl_xor_sync(FULL, vw, 2);
        vx += __shfl_xor_sync(FULL, vx, 4); vw += __shfl_xor_sync(FULL, vw, 4);
        vx += __shfl_xor_sync(FULL, vx, 8); vw += __shfl_xor_sync(FULL, vw, 8);
        if ((tid & 15) == 0) {
            int r = (tid >> 4) + 16 * it;
            sXn[r] = vx;
            sWn[r] = vw;
        }
    }
    __syncthreads();

    // dump accumulators (aliases staging)
    float* sO = dsmf;
    #pragma unroll
    for (int nt = 0; nt < 2; nt++)
        wmma::store_matrix_sync(sO + (wm * 16) * 64 + wn * 32 + nt * 16,
                                acc[nt], 64, wmma::mem_row_major);
    __syncthreads();

    // epilogue: one thread per row
    if (tid < 64) {
        const int row = r0 + tid;
        const float xn = sXn[tid];
        const float* dr = sO + tid * 64;
        float sv[64];
        float mx = 0.f;
        #pragma unroll
        for (int p = 0; p < PDIM; p++) {
            float d = xn - 2.f * dr[p] + sWn[p];
            float s = __expf(-sGam[p] * d) * sAlp[p];
            sv[p] = s;
            mx = fmaxf(mx, s);
        }
        float inv = 1.f / (mx + EPSV);
        float* orow = g_si + (size_t)row * PDIM;
        #pragma unroll
        for (int p4 = 0; p4 < PDIM; p4 += 4) {
            float4 o;
            o.x = sv[p4 + 0] * inv; o.y = sv[p4 + 1] * inv;
            o.z = sv[p4 + 2] * inv; o.w = sv[p4 + 3] * inv;
            *(float4*)(orow + p4) = o;
        }
    }
}

// ====== Dempster scan : 64 rows/block, 256 thr, 2-row groups, deferred norm ======
#define SSM_FLOATS (7168 + 64 * 68 + 64 * 102)

#define DS_STEP(P, APPLY, START) do {                                          \
    float sA_ = srowA[(P)], sB_ = srowB[(P)];                                  \
    float aA_ = 1.f - sA_,  aB_ = 1.f - sB_;                                   \
    if (APPLY) { sA_ *= pendA; aA_ *= pendA; sB_ *= pendB; aB_ *= pendB; }     \
    float g1A_ = sA_ * omA, g1B_ = sB_ * omB;                                  \
    omA = 3.f * aA_ * omA;  omB = 3.f * aB_ * omB;                             \
    ull spA_ = pk2(sA_, sA_), apA_ = pk2(aA_, aA_), gpA_ = pk2(g1A_, g1A_);    \
    ull spB_ = pk2(sB_, sB_), apB_ = pk2(aB_, aB_), gpB_ = pk2(g1B_, g1B_);    \
    const float* up_ = sU + (P) * USTRIDE + 2 * q;                             \
    _Pragma("unroll")                                                          \
    for (int i_ = 0; i_ < 7; i_++) {                                           \
        ull u2_ = *(const ull*)(up_ + 16 * i_);                                \
        mA[i_] = fma2(gpA_, u2_, mul2(mA[i_], fma2(spA_, u2_, apA_)));         \
        mB[i_] = fma2(gpB_, u2_, mul2(mB[i_], fma2(spB_, u2_, apB_)));         \
    }                                                                          \
    if (START) {                                                               \
        ull psA_ = mA[0], psB_ = mB[0];                                        \
        _Pragma("unroll")                                                      \
        for (int i_ = 1; i_ < 7; i_++) { psA_ = add2(psA_, mA[i_]); psB_ = add2(psB_, mB[i_]); } \
        float2 va_ = upk2(psA_), vb_ = upk2(psB_);                             \
        float pa_ = va_.x + va_.y, pb_ = vb_.x + vb_.y;                        \
        pa_ += __shfl_xor_sync(FULL, pa_, 1); pb_ += __shfl_xor_sync(FULL, pb_, 1); \
        pa_ += __shfl_xor_sync(FULL, pa_, 2); pb_ += __shfl_xor_sync(FULL, pb_, 2); \
        pa_ += __shfl_xor_sync(FULL, pa_, 4); pb_ += __shfl_xor_sync(FULL, pb_, 4); \
        pendA = frcp(pa_ + omA); pendB = frcp(pb_ + omB);                      \
    }                                                                          \
} while (0)

__global__ __launch_bounds__(256)
void scan_kernel(float* __restrict__ out) {
    extern __shared__ __align__(16) float ssm[];
    float* sU   = ssm;                    // 7168 floats
    float* sSi  = ssm + 7168;             // 64 rows x stride 68
    float* sOut = ssm + 7168 + 64 * 68;   // 64 rows x stride 102

    const int tid = threadIdx.x;
    const int r0  = blockIdx.x * 64;
    const unsigned FULL = 0xffffffffu;

    #pragma unroll
    for (int it = 0; it < 7; it++) {
        int f = tid + it * 256;
        *(float4*)(sU + f * 4) = *(const float4*)(g_u2 + f * 4);
    }
    #pragma unroll
    for (int it = 0; it < 4; it++) {
        int f = tid + it * 256;
        int r = f >> 4, c = f & 15;
        *(float4*)(sSi + r * 68 + c * 4) =
            *(const float4*)(g_si + (size_t)(r0 + r) * PDIM + c * 4);
    }
    __syncthreads();

    const int lane = tid & 31;
    const int warp = tid >> 5;          // 0..7
    const int g = lane >> 3;            // group: 2 rows
    const int q = lane & 7;             // pairs j = 2q + 16i
    const int rA = warp * 8 + g * 2;
    const int rB = rA + 1;
    const float* srowA = sSi + rA * 68;
    const float* srowB = sSi + rB * 68;

    ull mA[7], mB[7];
    float omA, omB, pendA = 1.f, pendB = 1.f;
    {
        float s0A = srowA[0], s0B = srowB[0];
        ull sA0 = pk2(s0A, s0A), sB0 = pk2(s0B, s0B);
        const float* u0 = sU + 2 * q;
        #pragma unroll
        for (int i = 0; i < 7; i++) {
            ull u2 = *(const ull*)(u0 + 16 * i);
            mA[i] = mul2(sA0, u2);
            mB[i] = mul2(sB0, u2);
        }
        omA = 1.f - s0A; omB = 1.f - s0B;
    }

    DS_STEP(1, false, false);
    DS_STEP(2, false, true);
    #pragma unroll 1
    for (int k = 0; k < 15; k++) {
        int p = 3 + (k << 2);
        DS_STEP(p,     false, false);
        DS_STEP(p + 1, true,  false);
        DS_STEP(p + 2, false, false);
        DS_STEP(p + 3, false, true);
    }
    DS_STEP(63, false, false);

    {
        ull psA = mA[0], psB = mB[0];
        #pragma unroll
        for (int i = 1; i < 7; i++) { psA = add2(psA, mA[i]); psB = add2(psB, mB[i]); }
        float2 va = upk2(psA), vb = upk2(psB);
        float fa = va.x + va.y, fb = vb.x + vb.y;
        fa += __shfl_xor_sync(FULL, fa, 1); fb += __shfl_xor_sync(FULL, fb, 1);
        fa += __shfl_xor_sync(FULL, fa, 2); fb += __shfl_xor_sync(FULL, fb, 2);
        fa += __shfl_xor_sync(FULL, fa, 4); fb += __shfl_xor_sync(FULL, fb, 4);
        float rnA = 1.f / (fa + omA), rnB = 1.f / (fb + omB);

        float* oA = sOut + rA * 102;
        float* oB = sOut + rB * 102;
        #pragma unroll
        for (int i = 0; i < 6; i++) {
            int j = 2 * q + 16 * i;
            float2 a = upk2(mA[i]), b = upk2(mB[i]);
            *(float2*)(oA + j) = make_float2(a.x * rnA, a.y * rnA);
            *(float2*)(oB + j) = make_float2(b.x * rnB, b.y * rnB);
        }
        int j = 96 + 2 * q;
        if (q < 2) {
            float2 a = upk2(mA[6]), b = upk2(mB[6]);
            *(float2*)(oA + j) = make_float2(a.x * rnA, a.y * rnA);
            *(float2*)(oB + j) = make_float2(b.x * rnB, b.y * rnB);
        } else if (q == 2) {
            oA[100] = omA * rnA;
            oB[100] = omB * rnB;
        }
    }
    __syncthreads();

    for (int idx = tid; idx < 64 * (CDIM + 1); idx += 256) {
        int rr = idx / (CDIM + 1);
        int jj = idx - rr * (CDIM + 1);
        out[(size_t)r0 * (CDIM + 1) + idx] = sOut[rr * 102 + jj];
    }
}

extern "C" void kernel_launch(void* const* d_in, const int* in_sizes, int n_in,
                              void* d_out, int out_size) {
    const float* x    = (const float*)d_in[0];
    const float* w    = (const float*)d_in[1];
    const float* xi   = (const float*)d_in[2];
    const float* eta  = (const float*)d_in[3];
    const float* beta = (const float*)d_in[4];
    float* out = (float*)d_out;

    cudaFuncSetAttribute(mma_si_kernel,
                         cudaFuncAttributeMaxDynamicSharedMemorySize, MSM_BYTES);
    cudaFuncSetAttribute(scan_kernel,
                         cudaFuncAttributeMaxDynamicSharedMemorySize, SSM_FLOATS * 4);

    mma_si_kernel<<<BROWS / 64 + 1, 256, MSM_BYTES>>>(x, w, xi, eta, beta);
    scan_kernel<<<BROWS / 64, 256, SSM_FLOATS * 4>>>(out);
}

// round 15
// speedup vs baseline: 1.0653x; 1.0653x over previous
#include <cuda_runtime.h>
#include <cuda_bf16.h>
#include <mma.h>
#include <cstdint>
#include <math.h>

using namespace nvcuda;

#define EPSV 1e-4f
#define BROWS 8192
#define FDIM 512
#define PDIM 64
#define CDIM 100
#define USTRIDE 112

typedef unsigned long long ull;

__device__ float g_si[BROWS * PDIM];
__device__ float g_u2[PDIM * USTRIDE];

// ---- packed f32x2 helpers (scan) ----
__device__ __forceinline__ ull pk2(float lo, float hi) {
    ull r; asm("mov.b64 %0, {%1, %2};" : "=l"(r) : "f"(lo), "f"(hi)); return r;
}
__device__ __forceinline__ float2 upk2(ull v) {
    float2 r; asm("mov.b64 {%0, %1}, %2;" : "=f"(r.x), "=f"(r.y) : "l"(v)); return r;
}
__device__ __forceinline__ ull fma2(ull a, ull b, ull c) {
    ull d; asm("fma.rn.f32x2 %0, %1, %2, %3;" : "=l"(d) : "l"(a), "l"(b), "l"(c)); return d;
}
__device__ __forceinline__ ull mul2(ull a, ull b) {
    ull d; asm("mul.rn.f32x2 %0, %1, %2;" : "=l"(d) : "l"(a), "l"(b)); return d;
}
__device__ __forceinline__ ull add2(ull a, ull b) {
    ull d; asm("add.rn.f32x2 %0, %1, %2;" : "=l"(d) : "l"(a), "l"(b)); return d;
}
__device__ __forceinline__ float frcp(float x) {
    float r; asm("rcp.approx.f32 %0, %1;" : "=f"(r) : "f"(x)); return r;
}

// truncation split: H = top-16-bit bf16 pair (PRMT), L = rn(v - hi) pair
__device__ __forceinline__ void tsplit4(float4 v, uint2& H, uint2& L) {
    unsigned u0 = __float_as_uint(v.x), u1 = __float_as_uint(v.y);
    unsigned u2 = __float_as_uint(v.z), u3 = __float_as_uint(v.w);
    H.x = __byte_perm(u0, u1, 0x7632);
    H.y = __byte_perm(u2, u3, 0x7632);
    float l0 = v.x - __uint_as_float(u0 & 0xFFFF0000u);
    float l1 = v.y - __uint_as_float(u1 & 0xFFFF0000u);
    float l2 = v.z - __uint_as_float(u2 & 0xFFFF0000u);
    float l3 = v.w - __uint_as_float(u3 & 0xFFFF0000u);
    asm("cvt.rn.bf16x2.f32 %0, %1, %2;" : "=r"(L.x) : "f"(l1), "f"(l0));
    asm("cvt.rn.bf16x2.f32 %0, %1, %2;" : "=r"(L.y) : "f"(l3), "f"(l2));
}

// ========== register-pipelined split + wmma GEMM + si : 256 threads ==========
// smem (bytes): sxh @0 (9216), sxl @9216, swh @18432, swl @27648 (stride 72 bf16)
//               consts @36864 (1 KB) ; sO f32 64x64 aliases @0
#define SM_XH 0
#define SM_XL 9216
#define SM_WH 18432
#define SM_WL 27648
#define SM_CON 36864
#define MSM_BYTES 37888
#define BSTR 72

__global__ __launch_bounds__(256)
void mma_si_kernel(const float* __restrict__ x, const float* __restrict__ w,
                   const float* __restrict__ xi, const float* __restrict__ eta,
                   const float* __restrict__ beta) {
    extern __shared__ __align__(128) char smem[];
    const int tid = threadIdx.x;

    // block 128: u table
    if (blockIdx.x == 128) {
        if (tid < PDIM) {
            const float* br = beta + (size_t)tid * CDIM;
            float* ur = g_u2 + tid * USTRIDE;
            float s2 = 0.f;
            #pragma unroll 4
            for (int c = 0; c < CDIM; c++) { float v = br[c]; float bb = v * v; ur[c] = bb; s2 += bb; }
            float rs = 1.f / s2;
            #pragma unroll 4
            for (int c = 0; c < CDIM; c++) ur[c] *= rs;
            #pragma unroll
            for (int c = CDIM; c < USTRIDE; c++) ur[c] = 0.f;
        }
        return;
    }

    __nv_bfloat16* sxh = (__nv_bfloat16*)(smem + SM_XH);
    __nv_bfloat16* sxl = (__nv_bfloat16*)(smem + SM_XL);
    __nv_bfloat16* swh = (__nv_bfloat16*)(smem + SM_WH);
    __nv_bfloat16* swl = (__nv_bfloat16*)(smem + SM_WL);
    float* sGam = (float*)(smem + SM_CON);
    float* sAlp = sGam + 64;
    float* sWn  = sAlp + 64;
    float* sXn  = sWn + 64;

    const int warp = tid >> 5;   // 0..7
    const int wm = warp >> 1;    // 0..3 (16-row slice)
    const int wn = warp & 1;     // 0..1 (32-col slice)
    const int r0 = blockIdx.x * 64;
    const unsigned FULL = 0xffffffffu;

    if (tid < PDIM) {
        float e = eta[tid];
        sGam[tid] = e * e;
        sAlp[tid] = 1.f / (1.f + __expf(-xi[tid]));
    }

    // per-thread slice addresses (4 x-float4 + 4 w-float4 per chunk)
    const int row = tid >> 2;            // f = tid + it*256 -> rows tid>>4 +16it? keep old map:
    // mapping: f = tid + it*256, row = f>>4, c4 = (f&15)<<2
    float4 bufA[8];   // current chunk: [0..3] x, [4..7] w
    float4 bufB[8];   // next chunk

    #pragma unroll
    for (int it = 0; it < 4; it++) {
        int f = tid + it * 256;
        int rr = f >> 4, c4 = (f & 15) << 2;
        bufA[it]     = __ldg((const float4*)(x + (size_t)(r0 + rr) * FDIM + c4));
        bufA[4 + it] = __ldg((const float4*)(w + (size_t)rr * FDIM + c4));
    }

    wmma::fragment<wmma::accumulator, 16, 16, 16, float> acc[2];
    #pragma unroll
    for (int nt = 0; nt < 2; nt++) wmma::fill_fragment(acc[nt], 0.f);

    float xnp[4] = {0.f, 0.f, 0.f, 0.f};
    float wnp[4] = {0.f, 0.f, 0.f, 0.f};

    #pragma unroll 1
    for (int ch = 0; ch < FDIM / 64; ch++) {
        // prefetch next chunk into the other register buffer
        if (ch < FDIM / 64 - 1) {
            int kc = (ch + 1) * 64;
            #pragma unroll
            for (int it = 0; it < 4; it++) {
                int f = tid + it * 256;
                int rr = f >> 4, c4 = (f & 15) << 2;
                bufB[it]     = __ldg((const float4*)(x + (size_t)(r0 + rr) * FDIM + kc + c4));
                bufB[4 + it] = __ldg((const float4*)(w + (size_t)rr * FDIM + kc + c4));
            }
        }

        // convert current registers -> bf16 tiles; accumulate norm partials
        #pragma unroll
        for (int it = 0; it < 4; it++) {
            int f = tid + it * 256;
            int rr = f >> 4, c = (f & 15) << 2;
            float4 v = bufA[it];
            uint2 H, L;
            tsplit4(v, H, L);
            *(uint2*)(sxh + rr * BSTR + c) = H;
            *(uint2*)(sxl + rr * BSTR + c) = L;
            xnp[it] += v.x * v.x + v.y * v.y + v.z * v.z + v.w * v.w;

            float4 u = bufA[4 + it];
            tsplit4(u, H, L);
            *(uint2*)(swh + rr * BSTR + c) = H;
            *(uint2*)(swl + rr * BSTR + c) = L;
            wnp[it] += u.x * u.x + u.y * u.y + u.z * u.z + u.w * u.w;
        }
        __syncthreads();   // tiles ready

        #pragma unroll
        for (int kk = 0; kk < 4; kk++) {
            wmma::fragment<wmma::matrix_a, 16, 16, 16, __nv_bfloat16, wmma::row_major> ah, al;
            wmma::load_matrix_sync(ah, sxh + wm * 16 * BSTR + kk * 16, BSTR);
            wmma::load_matrix_sync(al, sxl + wm * 16 * BSTR + kk * 16, BSTR);
            #pragma unroll
            for (int nt = 0; nt < 2; nt++) {
                int ncol = wn * 32 + nt * 16;
                wmma::fragment<wmma::matrix_b, 16, 16, 16, __nv_bfloat16, wmma::col_major> bh, bl;
                wmma::load_matrix_sync(bh, swh + ncol * BSTR + kk * 16, BSTR);
                wmma::load_matrix_sync(bl, swl + ncol * BSTR + kk * 16, BSTR);
                wmma::mma_sync(acc[nt], ah, bh, acc[nt]);
                wmma::mma_sync(acc[nt], ah, bl, acc[nt]);
                wmma::mma_sync(acc[nt], al, bh, acc[nt]);
            }
        }
        __syncthreads();   // mma done; tiles free for next conversion

        #pragma unroll
        for (int i = 0; i < 8; i++) bufA[i] = bufB[i];
    }

    // reduce norm partials: row (tid>>4) + 16*it, owned by 16 consecutive tids
    #pragma unroll
    for (int it = 0; it < 4; it++) {
        float vx = xnp[it], vw = wnp[it];
        vx += __shfl_xor_sync(FULL, vx, 1); vw += __shfl_xor_sync(FULL, vw, 1);
        vx += __shfl_xor_sync(FULL, vx, 2); vw += __shfl_xor_sync(FULL, vw, 2);
        vx += __shfl_xor_sync(FULL, vx, 4); vw += __shfl_xor_sync(FULL, vw, 4);
        vx += __shfl_xor_sync(FULL, vx, 8); vw += __shfl_xor_sync(FULL, vw, 8);
        if ((tid & 15) == 0) {
            int r = (tid >> 4) + 16 * it;
            sXn[r] = vx;
            sWn[r] = vw;
        }
    }
    __syncthreads();

    // dump accumulators (aliases tiles)
    float* sO = (float*)smem;
    #pragma unroll
    for (int nt = 0; nt < 2; nt++)
        wmma::store_matrix_sync(sO + (wm * 16) * 64 + wn * 32 + nt * 16,
                                acc[nt], 64, wmma::mem_row_major);
    __syncthreads();

    // epilogue: one thread per row
    if (tid < 64) {
        const int orow_i = r0 + tid;
        const float xn = sXn[tid];
        const float* dr = sO + tid * 64;
        float sv[64];
        float mx = 0.f;
        #pragma unroll
        for (int p = 0; p < PDIM; p++) {
            float d = xn - 2.f * dr[p] + sWn[p];
            float s = __expf(-sGam[p] * d) * sAlp[p];
            sv[p] = s;
            mx = fmaxf(mx, s);
        }
        float inv = 1.f / (mx + EPSV);
        float* orow = g_si + (size_t)orow_i * PDIM;
        #pragma unroll
        for (int p4 = 0; p4 < PDIM; p4 += 4) {
            float4 o;
            o.x = sv[p4 + 0] * inv; o.y = sv[p4 + 1] * inv;
            o.z = sv[p4 + 2] * inv; o.w = sv[p4 + 3] * inv;
            *(float4*)(orow + p4) = o;
        }
    }
}

// ====== Dempster scan : R13 config (32 rows, 128 thr, 2-row groups) ======
#define SSM_FLOATS (7168 + 32 * 68 + 32 * 102)

#define DS_STEP(P, APPLY, START) do {                                          \
    float sA_ = srowA[(P)], sB_ = srowB[(P)];                                  \
    float aA_ = 1.f - sA_,  aB_ = 1.f - sB_;                                   \
    if (APPLY) { sA_ *= pendA; aA_ *= pendA; sB_ *= pendB; aB_ *= pendB; }     \
    float g1A_ = sA_ * omA, g1B_ = sB_ * omB;                                  \
    omA = 3.f * aA_ * omA;  omB = 3.f * aB_ * omB;                             \
    ull spA_ = pk2(sA_, sA_), apA_ = pk2(aA_, aA_), gpA_ = pk2(g1A_, g1A_);    \
    ull spB_ = pk2(sB_, sB_), apB_ = pk2(aB_, aB_), gpB_ = pk2(g1B_, g1B_);    \
    const float* up_ = sU + (P) * USTRIDE + 2 * q;                             \
    _Pragma("unroll")                                                          \
    for (int i_ = 0; i_ < 7; i_++) {                                           \
        ull u2_ = *(const ull*)(up_ + 16 * i_);                                \
        mA[i_] = fma2(gpA_, u2_, mul2(mA[i_], fma2(spA_, u2_, apA_)));         \
        mB[i_] = fma2(gpB_, u2_, mul2(mB[i_], fma2(spB_, u2_, apB_)));         \
    }                                                                          \
    if (START) {                                                               \
        ull psA_ = mA[0], psB_ = mB[0];                                        \
        _Pragma("unroll")                                                      \
        for (int i_ = 1; i_ < 7; i_++) { psA_ = add2(psA_, mA[i_]); psB_ = add2(psB_, mB[i_]); } \
        float2 va_ = upk2(psA_), vb_ = upk2(psB_);                             \
        float pa_ = va_.x + va_.y, pb_ = vb_.x + vb_.y;                        \
        pa_ += __shfl_xor_sync(FULL, pa_, 1); pb_ += __shfl_xor_sync(FULL, pb_, 1); \
        pa_ += __shfl_xor_sync(FULL, pa_, 2); pb_ += __shfl_xor_sync(FULL, pb_, 2); \
        pa_ += __shfl_xor_sync(FULL, pa_, 4); pb_ += __shfl_xor_sync(FULL, pb_, 4); \
        pendA = frcp(pa_ + omA); pendB = frcp(pb_ + omB);                      \
    }                                                                          \
} while (0)

__global__ __launch_bounds__(128)
void scan_kernel(float* __restrict__ out) {
    extern __shared__ __align__(16) float ssm[];
    float* sU   = ssm;
    float* sSi  = ssm + 7168;
    float* sOut = ssm + 7168 + 32 * 68;

    const int tid = threadIdx.x;
    const int r0  = blockIdx.x * 32;
    const unsigned FULL = 0xffffffffu;

    #pragma unroll
    for (int it = 0; it < 14; it++) {
        int f = tid + it * 128;
        *(float4*)(sU + f * 4) = *(const float4*)(g_u2 + f * 4);
    }
    #pragma unroll
    for (int it = 0; it < 4; it++) {
        int f = tid + it * 128;
        int r = f >> 4, c = f & 15;
        *(float4*)(sSi + r * 68 + c * 4) =
            *(const float4*)(g_si + (size_t)(r0 + r) * PDIM + c * 4);
    }
    __syncthreads();

    const int lane = tid & 31;
    const int warp = tid >> 5;
    const int g = lane >> 3;
    const int q = lane & 7;
    const int rA = warp * 8 + g * 2;
    const int rB = rA + 1;
    const float* srowA = sSi + rA * 68;
    const float* srowB = sSi + rB * 68;

    ull mA[7], mB[7];
    float omA, omB, pendA = 1.f, pendB = 1.f;
    {
        float s0A = srowA[0], s0B = srowB[0];
        ull sA0 = pk2(s0A, s0A), sB0 = pk2(s0B, s0B);
        const float* u0 = sU + 2 * q;
        #pragma unroll
        for (int i = 0; i < 7; i++) {
            ull u2 = *(const ull*)(u0 + 16 * i);
            mA[i] = mul2(sA0, u2);
            mB[i] = mul2(sB0, u2);
        }
        omA = 1.f - s0A; omB = 1.f - s0B;
    }

    DS_STEP(1, false, false);
    DS_STEP(2, false, true);
    #pragma unroll 1
    for (int k = 0; k < 15; k++) {
        int p = 3 + (k << 2);
        DS_STEP(p,     false, false);
        DS_STEP(p + 1, true,  false);
        DS_STEP(p + 2, false, false);
        DS_STEP(p + 3, false, true);
    }
    DS_STEP(63, false, false);

    {
        ull psA = mA[0], psB = mB[0];
        #pragma unroll
        for (int i = 1; i < 7; i++) { psA = add2(psA, mA[i]); psB = add2(psB, mB[i]); }
        float2 va = upk2(psA), vb = upk2(psB);
        float fa = va.x + va.y, fb = vb.x + vb.y;
        fa += __shfl_xor_sync(FULL, fa, 1); fb += __shfl_xor_sync(FULL, fb, 1);
        fa += __shfl_xor_sync(FULL, fa, 2); fb += __shfl_xor_sync(FULL, fb, 2);
        fa += __shfl_xor_sync(FULL, fa, 4); fb += __shfl_xor_sync(FULL, fb, 4);
        float rnA = 1.f / (fa + omA), rnB = 1.f / (fb + omB);

        float* oA = sOut + rA * 102;
        float* oB = sOut + rB * 102;
        #pragma unroll
        for (int i = 0; i < 6; i++) {
            int j = 2 * q + 16 * i;
            float2 a = upk2(mA[i]), b = upk2(mB[i]);
            *(float2*)(oA + j) = make_float2(a.x * rnA, a.y * rnA);
            *(float2*)(oB + j) = make_float2(b.x * rnB, b.y * rnB);
        }
        int j = 96 + 2 * q;
        if (q < 2) {
            float2 a = upk2(mA[6]), b = upk2(mB[6]);
            *(float2*)(oA + j) = make_float2(a.x * rnA, a.y * rnA);
            *(float2*)(oB + j) = make_float2(b.x * rnB, b.y * rnB);
        } else if (q == 2) {
            oA[100] = omA * rnA;
            oB[100] = omB * rnB;
        }
    }
    __syncthreads();

    for (int idx = tid; idx < 32 * (CDIM + 1); idx += 128) {
        int rr = idx / (CDIM + 1);
        int jj = idx - rr * (CDIM + 1);
        out[(size_t)r0 * (CDIM + 1) + idx] = sOut[rr * 102 + jj];
    }
}

extern "C" void kernel_launch(void* const* d_in, const int* in_sizes, int n_in,
                              void* d_out, int out_size) {
    const float* x    = (const float*)d_in[0];
    const float* w    = (const float*)d_in[1];
    const float* xi   = (const float*)d_in[2];
    const float* eta  = (const float*)d_in[3];
    const float* beta = (const float*)d_in[4];
    float* out = (float*)d_out;

    cudaFuncSetAttribute(mma_si_kernel,
                         cudaFuncAttributeMaxDynamicSharedMemorySize, MSM_BYTES);
    cudaFuncSetAttribute(scan_kernel,
                         cudaFuncAttributeMaxDynamicSharedMemorySize, SSM_FLOATS * 4);

    mma_si_kernel<<<BROWS / 64 + 1, 256, MSM_BYTES>>>(x, w, xi, eta, beta);
    scan_kernel<<<BROWS / 32, 128, SSM_FLOATS * 4>>>(out);
}

// round 16
// speedup vs baseline: 1.2744x; 1.1963x over previous
#include <cuda_runtime.h>
#include <cuda_bf16.h>
#include <mma.h>
#include <cstdint>
#include <math.h>

using namespace nvcuda;

#define EPSV 1e-4f
#define BROWS 8192
#define FDIM 512
#define PDIM 64
#define CDIM 100
#define USTRIDE 112

typedef unsigned long long ull;

// ---- packed f32x2 helpers ----
__device__ __forceinline__ ull pk2(float lo, float hi) {
    ull r; asm("mov.b64 %0, {%1, %2};" : "=l"(r) : "f"(lo), "f"(hi)); return r;
}
__device__ __forceinline__ float2 upk2(ull v) {
    float2 r; asm("mov.b64 {%0, %1}, %2;" : "=f"(r.x), "=f"(r.y) : "l"(v)); return r;
}
__device__ __forceinline__ ull fma2(ull a, ull b, ull c) {
    ull d; asm("fma.rn.f32x2 %0, %1, %2, %3;" : "=l"(d) : "l"(a), "l"(b), "l"(c)); return d;
}
__device__ __forceinline__ ull mul2(ull a, ull b) {
    ull d; asm("mul.rn.f32x2 %0, %1, %2;" : "=l"(d) : "l"(a), "l"(b)); return d;
}
__device__ __forceinline__ ull add2(ull a, ull b) {
    ull d; asm("add.rn.f32x2 %0, %1, %2;" : "=l"(d) : "l"(a), "l"(b)); return d;
}
__device__ __forceinline__ float frcp(float x) {
    float r; asm("rcp.approx.f32 %0, %1;" : "=f"(r) : "f"(x)); return r;
}

// truncation split: H = top-16-bit bf16 pair (PRMT), L = rn(v - hi) pair
__device__ __forceinline__ void tsplit4(float4 v, uint2& H, uint2& L) {
    unsigned u0 = __float_as_uint(v.x), u1 = __float_as_uint(v.y);
    unsigned u2 = __float_as_uint(v.z), u3 = __float_as_uint(v.w);
    H.x = __byte_perm(u0, u1, 0x7632);
    H.y = __byte_perm(u2, u3, 0x7632);
    float l0 = v.x - __uint_as_float(u0 & 0xFFFF0000u);
    float l1 = v.y - __uint_as_float(u1 & 0xFFFF0000u);
    float l2 = v.z - __uint_as_float(u2 & 0xFFFF0000u);
    float l3 = v.w - __uint_as_float(u3 & 0xFFFF0000u);
    asm("cvt.rn.bf16x2.f32 %0, %1, %2;" : "=r"(L.x) : "f"(l1), "f"(l0));
    asm("cvt.rn.bf16x2.f32 %0, %1, %2;" : "=r"(L.y) : "f"(l3), "f"(l2));
}

// ================== fused mma + si + Dempster scan : one kernel ==================
// smem (bytes):
//   bf16 tiles  @0      : sxh 9216 | sxl @9216 | swh @18432 | swl @27648  (ends 36864)
//       (after mma: @0 reused for f32 acc dump 16384, then for sOut 64x102x4=26112)
//   consts      @36864  : sGam 256 | sAlp 256 | sWn 256 | sXn 256        (ends 37888)
//   sU          @37888  : 64 x 112 x 4 = 28672                            (ends 66560)
//   sSi         @66560  : 64 x 68 x 4 = 17408                             (ends 83968)
#define SM_XH 0
#define SM_XL 9216
#define SM_WH 18432
#define SM_WL 27648
#define SM_CON 36864
#define SM_U   37888
#define SM_SI  66560
#define MSM_BYTES 84096
#define BSTR 72

#define DS_STEP(P, APPLY, START) do {                                          \
    float sA_ = srowA[(P)], sB_ = srowB[(P)];                                  \
    float aA_ = 1.f - sA_,  aB_ = 1.f - sB_;                                   \
    if (APPLY) { sA_ *= pendA; aA_ *= pendA; sB_ *= pendB; aB_ *= pendB; }     \
    float g1A_ = sA_ * omA, g1B_ = sB_ * omB;                                  \
    omA = 3.f * aA_ * omA;  omB = 3.f * aB_ * omB;                             \
    ull spA_ = pk2(sA_, sA_), apA_ = pk2(aA_, aA_), gpA_ = pk2(g1A_, g1A_);    \
    ull spB_ = pk2(sB_, sB_), apB_ = pk2(aB_, aB_), gpB_ = pk2(g1B_, g1B_);    \
    const float* up_ = sU + (P) * USTRIDE + 2 * q;                             \
    _Pragma("unroll")                                                          \
    for (int i_ = 0; i_ < 7; i_++) {                                           \
        ull u2_ = *(const ull*)(up_ + 16 * i_);                                \
        mA[i_] = fma2(gpA_, u2_, mul2(mA[i_], fma2(spA_, u2_, apA_)));         \
        mB[i_] = fma2(gpB_, u2_, mul2(mB[i_], fma2(spB_, u2_, apB_)));         \
    }                                                                          \
    if (START) {                                                               \
        ull psA_ = mA[0], psB_ = mB[0];                                        \
        _Pragma("unroll")                                                      \
        for (int i_ = 1; i_ < 7; i_++) { psA_ = add2(psA_, mA[i_]); psB_ = add2(psB_, mB[i_]); } \
        float2 va_ = upk2(psA_), vb_ = upk2(psB_);                             \
        float pa_ = va_.x + va_.y, pb_ = vb_.x + vb_.y;                        \
        pa_ += __shfl_xor_sync(FULL, pa_, 1); pb_ += __shfl_xor_sync(FULL, pb_, 1); \
        pa_ += __shfl_xor_sync(FULL, pa_, 2); pb_ += __shfl_xor_sync(FULL, pb_, 2); \
        pa_ += __shfl_xor_sync(FULL, pa_, 4); pb_ += __shfl_xor_sync(FULL, pb_, 4); \
        pendA = frcp(pa_ + omA); pendB = frcp(pb_ + omB);                      \
    }                                                                          \
} while (0)

__global__ __launch_bounds__(256)
void fused_kernel(const float* __restrict__ x, const float* __restrict__ w,
                  const float* __restrict__ xi, const float* __restrict__ eta,
                  const float* __restrict__ beta, float* __restrict__ out) {
    extern __shared__ __align__(128) char smem[];
    const int tid = threadIdx.x;
    const int warp = tid >> 5;   // 0..7
    const int lane = tid & 31;
    const int wm = warp >> 1;    // 0..3 (16-row slice)
    const int wn = warp & 1;     // 0..1 (32-col slice)
    const int r0 = blockIdx.x * 64;
    const unsigned FULL = 0xffffffffu;

    __nv_bfloat16* sxh = (__nv_bfloat16*)(smem + SM_XH);
    __nv_bfloat16* sxl = (__nv_bfloat16*)(smem + SM_XL);
    __nv_bfloat16* swh = (__nv_bfloat16*)(smem + SM_WH);
    __nv_bfloat16* swl = (__nv_bfloat16*)(smem + SM_WL);
    float* sGam = (float*)(smem + SM_CON);
    float* sAlp = sGam + 64;
    float* sWn  = sAlp + 64;
    float* sXn  = sWn + 64;
    float* sU   = (float*)(smem + SM_U);
    float* sSi  = (float*)(smem + SM_SI);

    // ---- prefetch chunk 0 into registers ----
    float4 bufA[8], bufB[8];
    #pragma unroll
    for (int it = 0; it < 4; it++) {
        int f = tid + it * 256;
        int rr = f >> 4, c4 = (f & 15) << 2;
        bufA[it]     = __ldg((const float4*)(x + (size_t)(r0 + rr) * FDIM + c4));
        bufA[4 + it] = __ldg((const float4*)(w + (size_t)rr * FDIM + c4));
    }

    // ---- per-block constants + u table (overlaps LDG latency) ----
    if (tid < PDIM) {
        float e = __ldg(eta + tid);
        sGam[tid] = e * e;
        sAlp[tid] = 1.f / (1.f + __expf(-__ldg(xi + tid)));
    }
    {
        #pragma unroll 1
        for (int rr = 0; rr < 8; rr++) {
            int row = warp * 8 + rr;
            const float* br = beta + (size_t)row * CDIM;
            float v0 = __ldg(br + lane),      bb0 = v0 * v0;
            float v1 = __ldg(br + lane + 32), bb1 = v1 * v1;
            float v2 = __ldg(br + lane + 64), bb2 = v2 * v2;
            float bb3 = 0.f;
            if (lane < 4) { float v3 = __ldg(br + lane + 96); bb3 = v3 * v3; }
            float s2 = bb0 + bb1 + bb2 + bb3;
            #pragma unroll
            for (int m = 16; m; m >>= 1) s2 += __shfl_xor_sync(FULL, s2, m);
            float rs = 1.f / s2;
            float* ur = sU + row * USTRIDE;
            ur[lane] = bb0 * rs; ur[lane + 32] = bb1 * rs; ur[lane + 64] = bb2 * rs;
            if (lane < 4) ur[lane + 96] = bb3 * rs;
            if (lane >= 4 && lane < 16) ur[96 + lane] = 0.f;
        }
    }

    // ---- mma mainloop (register-pipelined split, R15) ----
    wmma::fragment<wmma::accumulator, 16, 16, 16, float> acc[2];
    #pragma unroll
    for (int nt = 0; nt < 2; nt++) wmma::fill_fragment(acc[nt], 0.f);
    float xnp[4] = {0.f, 0.f, 0.f, 0.f};
    float wnp[4] = {0.f, 0.f, 0.f, 0.f};

    #pragma unroll 1
    for (int ch = 0; ch < FDIM / 64; ch++) {
        if (ch < FDIM / 64 - 1) {
            int kc = (ch + 1) * 64;
            #pragma unroll
            for (int it = 0; it < 4; it++) {
                int f = tid + it * 256;
                int rr = f >> 4, c4 = (f & 15) << 2;
                bufB[it]     = __ldg((const float4*)(x + (size_t)(r0 + rr) * FDIM + kc + c4));
                bufB[4 + it] = __ldg((const float4*)(w + (size_t)rr * FDIM + kc + c4));
            }
        }

        #pragma unroll
        for (int it = 0; it < 4; it++) {
            int f = tid + it * 256;
            int rr = f >> 4, c = (f & 15) << 2;
            float4 v = bufA[it];
            uint2 H, L;
            tsplit4(v, H, L);
            *(uint2*)(sxh + rr * BSTR + c) = H;
            *(uint2*)(sxl + rr * BSTR + c) = L;
            xnp[it] += v.x * v.x + v.y * v.y + v.z * v.z + v.w * v.w;

            float4 u = bufA[4 + it];
            tsplit4(u, H, L);
            *(uint2*)(swh + rr * BSTR + c) = H;
            *(uint2*)(swl + rr * BSTR + c) = L;
            wnp[it] += u.x * u.x + u.y * u.y + u.z * u.z + u.w * u.w;
        }
        __syncthreads();   // tiles ready

        #pragma unroll
        for (int kk = 0; kk < 4; kk++) {
            wmma::fragment<wmma::matrix_a, 16, 16, 16, __nv_bfloat16, wmma::row_major> ah, al;
            wmma::load_matrix_sync(ah, sxh + wm * 16 * BSTR + kk * 16, BSTR);
            wmma::load_matrix_sync(al, sxl + wm * 16 * BSTR + kk * 16, BSTR);
            #pragma unroll
            for (int nt = 0; nt < 2; nt++) {
                int ncol = wn * 32 + nt * 16;
                wmma::fragment<wmma::matrix_b, 16, 16, 16, __nv_bfloat16, wmma::col_major> bh, bl;
                wmma::load_matrix_sync(bh, swh + ncol * BSTR + kk * 16, BSTR);
                wmma::load_matrix_sync(bl, swl + ncol * BSTR + kk * 16, BSTR);
                wmma::mma_sync(acc[nt], ah, bh, acc[nt]);
                wmma::mma_sync(acc[nt], ah, bl, acc[nt]);
                wmma::mma_sync(acc[nt], al, bh, acc[nt]);
            }
        }
        __syncthreads();   // mma done; tiles free

        #pragma unroll
        for (int i = 0; i < 8; i++) bufA[i] = bufB[i];
    }

    // ---- norm partial reduction ----
    #pragma unroll
    for (int it = 0; it < 4; it++) {
        float vx = xnp[it], vw = wnp[it];
        vx += __shfl_xor_sync(FULL, vx, 1); vw += __shfl_xor_sync(FULL, vw, 1);
        vx += __shfl_xor_sync(FULL, vx, 2); vw += __shfl_xor_sync(FULL, vw, 2);
        vx += __shfl_xor_sync(FULL, vx, 4); vw += __shfl_xor_sync(FULL, vw, 4);
        vx += __shfl_xor_sync(FULL, vx, 8); vw += __shfl_xor_sync(FULL, vw, 8);
        if ((tid & 15) == 0) {
            int r = (tid >> 4) + 16 * it;
            sXn[r] = vx;
            sWn[r] = vw;
        }
    }
    __syncthreads();

    // ---- dump accumulators (aliases tiles @0) ----
    float* sO = (float*)smem;
    #pragma unroll
    for (int nt = 0; nt < 2; nt++)
        wmma::store_matrix_sync(sO + (wm * 16) * 64 + wn * 32 + nt * 16,
                                acc[nt], 64, wmma::mem_row_major);
    __syncthreads();

    // ---- si epilogue: one thread per row, straight into sSi ----
    if (tid < 64) {
        const float xn = sXn[tid];
        const float* dr = sO + tid * 64;
        float* srow = sSi + tid * 68;
        float sv[64];
        float mx = 0.f;
        #pragma unroll
        for (int p = 0; p < PDIM; p++) {
            float d = xn - 2.f * dr[p] + sWn[p];
            float s = __expf(-sGam[p] * d) * sAlp[p];
            sv[p] = s;
            mx = fmaxf(mx, s);
        }
        float inv = 1.f / (mx + EPSV);
        #pragma unroll
        for (int p = 0; p < PDIM; p++) srow[p] = sv[p] * inv;
    }
    __syncthreads();

    // ---- Dempster scan (R14 core: 2 rows per 8-lane group, deferred norm) ----
    const int g = lane >> 3;
    const int q = lane & 7;
    const int rA = warp * 8 + g * 2;
    const int rB = rA + 1;
    const float* srowA = sSi + rA * 68;
    const float* srowB = sSi + rB * 68;
    float* sOut = (float*)smem;   // aliases sO/tiles (scan reads only sSi/sU)

    ull mA[7], mB[7];
    float omA, omB, pendA = 1.f, pendB = 1.f;
    {
        float s0A = srowA[0], s0B = srowB[0];
        ull sA0 = pk2(s0A, s0A), sB0 = pk2(s0B, s0B);
        const float* u0 = sU + 2 * q;
        #pragma unroll
        for (int i = 0; i < 7; i++) {
            ull u2 = *(const ull*)(u0 + 16 * i);
            mA[i] = mul2(sA0, u2);
            mB[i] = mul2(sB0, u2);
        }
        omA = 1.f - s0A; omB = 1.f - s0B;
    }

    DS_STEP(1, false, false);
    DS_STEP(2, false, true);
    #pragma unroll 1
    for (int k = 0; k < 15; k++) {
        int p = 3 + (k << 2);
        DS_STEP(p,     false, false);
        DS_STEP(p + 1, true,  false);
        DS_STEP(p + 2, false, false);
        DS_STEP(p + 3, false, true);
    }
    DS_STEP(63, false, false);

    {
        ull psA = mA[0], psB = mB[0];
        #pragma unroll
        for (int i = 1; i < 7; i++) { psA = add2(psA, mA[i]); psB = add2(psB, mB[i]); }
        float2 va = upk2(psA), vb = upk2(psB);
        float fa = va.x + va.y, fb = vb.x + vb.y;
        fa += __shfl_xor_sync(FULL, fa, 1); fb += __shfl_xor_sync(FULL, fb, 1);
        fa += __shfl_xor_sync(FULL, fa, 2); fb += __shfl_xor_sync(FULL, fb, 2);
        fa += __shfl_xor_sync(FULL, fa, 4); fb += __shfl_xor_sync(FULL, fb, 4);
        float rnA = 1.f / (fa + omA), rnB = 1.f / (fb + omB);

        float* oA = sOut + rA * 102;
        float* oB = sOut + rB * 102;
        #pragma unroll
        for (int i = 0; i < 6; i++) {
            int j = 2 * q + 16 * i;
            float2 a = upk2(mA[i]), b = upk2(mB[i]);
            *(float2*)(oA + j) = make_float2(a.x * rnA, a.y * rnA);
            *(float2*)(oB + j) = make_float2(b.x * rnB, b.y * rnB);
        }
        int j = 96 + 2 * q;
        if (q < 2) {
            float2 a = upk2(mA[6]), b = upk2(mB[6]);
            *(float2*)(oA + j) = make_float2(a.x * rnA, a.y * rnA);
            *(float2*)(oB + j) = make_float2(b.x * rnB, b.y * rnB);
        } else if (q == 2) {
            oA[100] = omA * rnA;
            oB[100] = omB * rnB;
        }
    }
    __syncthreads();

    // ---- coalesced output (64 rows x 101) ----
    for (int idx = tid; idx < 64 * (CDIM + 1); idx += 256) {
        int rr = idx / (CDIM + 1);
        int jj = idx - rr * (CDIM + 1);
        out[(size_t)r0 * (CDIM + 1) + idx] = sOut[rr * 102 + jj];
    }
}

extern "C" void kernel_launch(void* const* d_in, const int* in_sizes, int n_in,
                              void* d_out, int out_size) {
    const float* x    = (const float*)d_in[0];
    const float* w    = (const float*)d_in[1];
    const float* xi   = (const float*)d_in[2];
    const float* eta  = (const float*)d_in[3];
    const float* beta = (const float*)d_in[4];
    float* out = (float*)d_out;

    cudaFuncSetAttribute(fused_kernel,
                         cudaFuncAttributeMaxDynamicSharedMemorySize, MSM_BYTES);
    fused_kernel<<<BROWS / 64, 256, MSM_BYTES>>>(x, w, xi, eta, beta, out);
}

// round 17
// speedup vs baseline: 1.2912x; 1.0132x over previous
#include <cuda_runtime.h>
#include <cuda_bf16.h>
#include <mma.h>
#include <cstdint>
#include <math.h>

using namespace nvcuda;

#define EPSV 1e-4f
#define BROWS 8192
#define FDIM 512
#define PDIM 64
#define CDIM 100
#define USTRIDE 112

typedef unsigned long long ull;

// ---- packed f32x2 helpers ----
__device__ __forceinline__ ull pk2(float lo, float hi) {
    ull r; asm("mov.b64 %0, {%1, %2};" : "=l"(r) : "f"(lo), "f"(hi)); return r;
}
__device__ __forceinline__ float2 upk2(ull v) {
    float2 r; asm("mov.b64 {%0, %1}, %2;" : "=f"(r.x), "=f"(r.y) : "l"(v)); return r;
}
__device__ __forceinline__ ull fma2(ull a, ull b, ull c) {
    ull d; asm("fma.rn.f32x2 %0, %1, %2, %3;" : "=l"(d) : "l"(a), "l"(b), "l"(c)); return d;
}
__device__ __forceinline__ ull mul2(ull a, ull b) {
    ull d; asm("mul.rn.f32x2 %0, %1, %2;" : "=l"(d) : "l"(a), "l"(b)); return d;
}
__device__ __forceinline__ ull add2(ull a, ull b) {
    ull d; asm("add.rn.f32x2 %0, %1, %2;" : "=l"(d) : "l"(a), "l"(b)); return d;
}
__device__ __forceinline__ float frcp(float x) {
    float r; asm("rcp.approx.f32 %0, %1;" : "=f"(r) : "f"(x)); return r;
}

// truncation split: H = top-16-bit bf16 pair (PRMT), L = rn(v - hi) pair
__device__ __forceinline__ void tsplit4(float4 v, uint2& H, uint2& L) {
    unsigned u0 = __float_as_uint(v.x), u1 = __float_as_uint(v.y);
    unsigned u2 = __float_as_uint(v.z), u3 = __float_as_uint(v.w);
    H.x = __byte_perm(u0, u1, 0x7632);
    H.y = __byte_perm(u2, u3, 0x7632);
    float l0 = v.x - __uint_as_float(u0 & 0xFFFF0000u);
    float l1 = v.y - __uint_as_float(u1 & 0xFFFF0000u);
    float l2 = v.z - __uint_as_float(u2 & 0xFFFF0000u);
    float l3 = v.w - __uint_as_float(u3 & 0xFFFF0000u);
    asm("cvt.rn.bf16x2.f32 %0, %1, %2;" : "=r"(L.x) : "f"(l1), "f"(l0));
    asm("cvt.rn.bf16x2.f32 %0, %1, %2;" : "=r"(L.y) : "f"(l3), "f"(l2));
}

// ================== fused mma + si + scan : 512 threads ==================
#define SM_XH 0
#define SM_XL 9216
#define SM_WH 18432
#define SM_WL 27648
#define SM_CON 36864
#define SM_U   37888
#define SM_SI  66560
#define MSM_BYTES 84096
#define BSTR 72

// single-row DS step with deferred normalization
#define DS_STEP(P, APPLY, START) do {                                          \
    float s_ = srow[(P)];                                                      \
    float a_ = 1.f - s_;                                                       \
    if (APPLY) { s_ *= pend; a_ *= pend; }                                     \
    float g1_ = s_ * om;                                                       \
    om = 3.f * a_ * om;                                                        \
    ull sp_ = pk2(s_, s_), ap_ = pk2(a_, a_), gp_ = pk2(g1_, g1_);             \
    const float* up_ = sU + (P) * USTRIDE + 2 * q;                             \
    _Pragma("unroll")                                                          \
    for (int i_ = 0; i_ < 7; i_++) {                                           \
        ull u2_ = *(const ull*)(up_ + 16 * i_);                                \
        m[i_] = fma2(gp_, u2_, mul2(m[i_], fma2(sp_, u2_, ap_)));              \
    }                                                                          \
    if (START) {                                                               \
        ull ps_ = m[0];                                                        \
        _Pragma("unroll")                                                      \
        for (int i_ = 1; i_ < 7; i_++) ps_ = add2(ps_, m[i_]);                 \
        float2 pv_ = upk2(ps_);                                                \
        float pa_ = pv_.x + pv_.y;                                             \
        pa_ += __shfl_xor_sync(FULL, pa_, 1);                                  \
        pa_ += __shfl_xor_sync(FULL, pa_, 2);                                  \
        pa_ += __shfl_xor_sync(FULL, pa_, 4);                                  \
        pend = frcp(pa_ + om);                                                 \
    }                                                                          \
} while (0)

__global__ __launch_bounds__(512)
void fused_kernel(const float* __restrict__ x, const float* __restrict__ w,
                  const float* __restrict__ xi, const float* __restrict__ eta,
                  const float* __restrict__ beta, float* __restrict__ out) {
    extern __shared__ __align__(128) char smem[];
    const int tid = threadIdx.x;
    const int warp = tid >> 5;   // 0..15
    const int lane = tid & 31;
    const int wm = warp >> 2;    // 0..3 (16-row slice)
    const int wn = warp & 3;     // 0..3 (16-col slice)
    const int r0 = blockIdx.x * 64;
    const unsigned FULL = 0xffffffffu;

    __nv_bfloat16* sxh = (__nv_bfloat16*)(smem + SM_XH);
    __nv_bfloat16* sxl = (__nv_bfloat16*)(smem + SM_XL);
    __nv_bfloat16* swh = (__nv_bfloat16*)(smem + SM_WH);
    __nv_bfloat16* swl = (__nv_bfloat16*)(smem + SM_WL);
    float* sGam = (float*)(smem + SM_CON);
    float* sAlp = sGam + 64;
    float* sWn  = sAlp + 64;
    float* sXn  = sWn + 64;
    float* sU   = (float*)(smem + SM_U);
    float* sSi  = (float*)(smem + SM_SI);

    // ---- prefetch chunk 0 into registers ([0..1] x, [2..3] w) ----
    float4 bufA[4], bufB[4];
    #pragma unroll
    for (int it = 0; it < 2; it++) {
        int f = tid + it * 512;
        int rr = f >> 4, c4 = (f & 15) << 2;
        bufA[it]     = __ldg((const float4*)(x + (size_t)(r0 + rr) * FDIM + c4));
        bufA[2 + it] = __ldg((const float4*)(w + (size_t)rr * FDIM + c4));
    }

    // ---- per-block constants + u table (overlaps LDG latency) ----
    if (tid < PDIM) {
        float e = __ldg(eta + tid);
        sGam[tid] = e * e;
        sAlp[tid] = 1.f / (1.f + __expf(-__ldg(xi + tid)));
    }
    {
        #pragma unroll 1
        for (int rr = 0; rr < 4; rr++) {
            int row = warp * 4 + rr;
            const float* br = beta + (size_t)row * CDIM;
            float v0 = __ldg(br + lane),      bb0 = v0 * v0;
            float v1 = __ldg(br + lane + 32), bb1 = v1 * v1;
            float v2 = __ldg(br + lane + 64), bb2 = v2 * v2;
            float bb3 = 0.f;
            if (lane < 4) { float v3 = __ldg(br + lane + 96); bb3 = v3 * v3; }
            float s2 = bb0 + bb1 + bb2 + bb3;
            #pragma unroll
            for (int m = 16; m; m >>= 1) s2 += __shfl_xor_sync(FULL, s2, m);
            float rs = 1.f / s2;
            float* ur = sU + row * USTRIDE;
            ur[lane] = bb0 * rs; ur[lane + 32] = bb1 * rs; ur[lane + 64] = bb2 * rs;
            if (lane < 4) ur[lane + 96] = bb3 * rs;
            if (lane >= 4 && lane < 16) ur[96 + lane] = 0.f;
        }
    }

    // ---- mma mainloop ----
    wmma::fragment<wmma::accumulator, 16, 16, 16, float> acc;
    wmma::fill_fragment(acc, 0.f);
    float xnp[2] = {0.f, 0.f};
    float wnp[2] = {0.f, 0.f};

    #pragma unroll 1
    for (int ch = 0; ch < FDIM / 64; ch++) {
        if (ch < FDIM / 64 - 1) {
            int kc = (ch + 1) * 64;
            #pragma unroll
            for (int it = 0; it < 2; it++) {
                int f = tid + it * 512;
                int rr = f >> 4, c4 = (f & 15) << 2;
                bufB[it]     = __ldg((const float4*)(x + (size_t)(r0 + rr) * FDIM + kc + c4));
                bufB[2 + it] = __ldg((const float4*)(w + (size_t)rr * FDIM + kc + c4));
            }
        }

        #pragma unroll
        for (int it = 0; it < 2; it++) {
            int f = tid + it * 512;
            int rr = f >> 4, c = (f & 15) << 2;
            float4 v = bufA[it];
            uint2 H, L;
            tsplit4(v, H, L);
            *(uint2*)(sxh + rr * BSTR + c) = H;
            *(uint2*)(sxl + rr * BSTR + c) = L;
            xnp[it] += v.x * v.x + v.y * v.y + v.z * v.z + v.w * v.w;

            float4 u = bufA[2 + it];
            tsplit4(u, H, L);
            *(uint2*)(swh + rr * BSTR + c) = H;
            *(uint2*)(swl + rr * BSTR + c) = L;
            wnp[it] += u.x * u.x + u.y * u.y + u.z * u.z + u.w * u.w;
        }
        __syncthreads();   // tiles ready

        #pragma unroll
        for (int kk = 0; kk < 4; kk++) {
            wmma::fragment<wmma::matrix_a, 16, 16, 16, __nv_bfloat16, wmma::row_major> ah, al;
            wmma::load_matrix_sync(ah, sxh + wm * 16 * BSTR + kk * 16, BSTR);
            wmma::load_matrix_sync(al, sxl + wm * 16 * BSTR + kk * 16, BSTR);
            wmma::fragment<wmma::matrix_b, 16, 16, 16, __nv_bfloat16, wmma::col_major> bh, bl;
            wmma::load_matrix_sync(bh, swh + wn * 16 * BSTR + kk * 16, BSTR);
            wmma::load_matrix_sync(bl, swl + wn * 16 * BSTR + kk * 16, BSTR);
            wmma::mma_sync(acc, ah, bh, acc);
            wmma::mma_sync(acc, ah, bl, acc);
            wmma::mma_sync(acc, al, bh, acc);
        }
        __syncthreads();   // mma done; tiles free

        #pragma unroll
        for (int i = 0; i < 4; i++) bufA[i] = bufB[i];
    }

    // ---- norm partial reduction: row (tid>>4)+32*it, 16 consecutive tids ----
    #pragma unroll
    for (int it = 0; it < 2; it++) {
        float vx = xnp[it], vw = wnp[it];
        vx += __shfl_xor_sync(FULL, vx, 1); vw += __shfl_xor_sync(FULL, vw, 1);
        vx += __shfl_xor_sync(FULL, vx, 2); vw += __shfl_xor_sync(FULL, vw, 2);
        vx += __shfl_xor_sync(FULL, vx, 4); vw += __shfl_xor_sync(FULL, vw, 4);
        vx += __shfl_xor_sync(FULL, vx, 8); vw += __shfl_xor_sync(FULL, vw, 8);
        if ((tid & 15) == 0) {
            int r = (tid >> 4) + 32 * it;
            sXn[r] = vx;
            sWn[r] = vw;
        }
    }
    __syncthreads();

    // ---- dump accumulators (aliases tiles @0) ----
    float* sO = (float*)smem;
    wmma::store_matrix_sync(sO + (wm * 16) * 64 + wn * 16, acc, 64, wmma::mem_row_major);
    __syncthreads();

    // ---- si epilogue: one thread per row -> sSi ----
    if (tid < 64) {
        const float xn = sXn[tid];
        const float* dr = sO + tid * 64;
        float* srow = sSi + tid * 68;
        float sv[64];
        float mx = 0.f;
        #pragma unroll
        for (int p = 0; p < PDIM; p++) {
            float d = xn - 2.f * dr[p] + sWn[p];
            float s = __expf(-sGam[p] * d) * sAlp[p];
            sv[p] = s;
            mx = fmaxf(mx, s);
        }
        float inv = 1.f / (mx + EPSV);
        #pragma unroll
        for (int p = 0; p < PDIM; p++) srow[p] = sv[p] * inv;
    }
    __syncthreads();

    // ---- Dempster scan: 16 warps x 4 rows, 1 row per 8-lane group ----
    const int g = lane >> 3;
    const int q = lane & 7;
    const int r = warp * 4 + g;
    const float* srow = sSi + r * 68;
    float* sOut = (float*)smem;   // aliases tiles/sO

    ull m[7];
    float om, pend = 1.f;
    {
        float s0 = srow[0];
        ull s0p = pk2(s0, s0);
        const float* u0 = sU + 2 * q;
        #pragma unroll
        for (int i = 0; i < 7; i++)
            m[i] = mul2(s0p, *(const ull*)(u0 + 16 * i));
        om = 1.f - s0;
    }

    DS_STEP(1, false, false);
    DS_STEP(2, false, true);
    #pragma unroll 1
    for (int k = 0; k < 15; k++) {
        int p = 3 + (k << 2);
        DS_STEP(p,     false, false);
        DS_STEP(p + 1, true,  false);
        DS_STEP(p + 2, false, false);
        DS_STEP(p + 3, false, true);
    }
    DS_STEP(63, false, false);

    {
        ull ps = m[0];
        #pragma unroll
        for (int i = 1; i < 7; i++) ps = add2(ps, m[i]);
        float2 pv = upk2(ps);
        float fs = pv.x + pv.y;
        fs += __shfl_xor_sync(FULL, fs, 1);
        fs += __shfl_xor_sync(FULL, fs, 2);
        fs += __shfl_xor_sync(FULL, fs, 4);
        float rn = 1.f / (fs + om);

        float* orow = sOut + r * 102;
        #pragma unroll
        for (int i = 0; i < 6; i++) {
            int j = 2 * q + 16 * i;
            float2 a = upk2(m[i]);
            *(float2*)(orow + j) = make_float2(a.x * rn, a.y * rn);
        }
        int j = 96 + 2 * q;
        if (q < 2) {
            float2 a = upk2(m[6]);
            *(float2*)(orow + j) = make_float2(a.x * rn, a.y * rn);
        } else if (q == 2) {
            orow[100] = om * rn;
        }
    }
    __syncthreads();

    // ---- coalesced output (64 rows x 101) ----
    for (int idx = tid; idx < 64 * (CDIM + 1); idx += 512) {
        int rr = idx / (CDIM + 1);
        int jj = idx - rr * (CDIM + 1);
        out[(size_t)r0 * (CDIM + 1) + idx] = sOut[rr * 102 + jj];
    }
}

extern "C" void kernel_launch(void* const* d_in, const int* in_sizes, int n_in,
                              void* d_out, int out_size) {
    const float* x    = (const float*)d_in[0];
    const float* w    = (const float*)d_in[1];
    const float* xi   = (const float*)d_in[2];
    const float* eta  = (const float*)d_in[3];
    const float* beta = (const float*)d_in[4];
    float* out = (float*)d_out;

    cudaFuncSetAttribute(fused_kernel,
                         cudaFuncAttributeMaxDynamicSharedMemorySize, MSM_BYTES);
    fused_kernel<<<BROWS / 64, 512, MSM_BYTES>>>(x, w, xi, eta, beta, out);
}